// round 15
// baseline (speedup 1.0000x reference)
#include <cuda_runtime.h>
#include <cuda_bf16.h>
#include <cstdint>
#include <math.h>

#define MAX_N 500000
#define MAX_E 1000000
#define HDIM  64
#define SCAN_T 512
#define SCAN_ITEMS 1024
#define POOL_BLOCKS 2960

// ---------------- device scratch ----------------
__device__ __nv_bfloat16 g_m0[(size_t)MAX_N * HDIM];  // layer-2 messages (bf16)
__device__ __nv_bfloat16 g_m1[(size_t)MAX_N * HDIM];  // layer-3 messages (bf16)
__device__ float g_dinv[MAX_N];
__device__ float4 g_xs4[MAX_N];
__device__ int   g_degi[MAX_N];
__device__ int   g_rowptr[MAX_N + 1];
__device__ int   g_erank[MAX_E];
__device__ int   g_esrc[MAX_E];
__device__ int   g_bsum[1024];
__device__ float g_partial[(size_t)POOL_BLOCKS * HDIM];
__device__ float g_pool[HDIM];

// ---------------- helpers ----------------
__device__ __forceinline__ unsigned pack_bf16x2(float lo, float hi) {
    unsigned r;
    asm("cvt.rn.bf16x2.f32 %0, %1, %2;" : "=r"(r) : "f"(hi), "f"(lo));
    return r;
}
__device__ __forceinline__ void acc_bf16x2(float& a0, float& a1, unsigned v) {
    __nv_bfloat162 b = *reinterpret_cast<__nv_bfloat162*>(&v);
    float2 f = __bfloat1622float2(b);
    a0 += f.x; a1 += f.y;
}
__device__ __forceinline__ void acc_uint4(float* a, uint4 v) {
    acc_bf16x2(a[0], a[1], v.x);
    acc_bf16x2(a[2], a[3], v.y);
    acc_bf16x2(a[4], a[5], v.z);
    acc_bf16x2(a[6], a[7], v.w);
}
__device__ __forceinline__ uint32_t f2tf32(float f) {
    uint32_t r;
    asm("cvt.rna.tf32.f32 %0, %1;" : "=r"(r) : "f"(f));
    return r;
}
__device__ __forceinline__ void mma_tf32(float* d, uint32_t a0, uint32_t a1, uint32_t a2,
                                         uint32_t a3, uint32_t b0, uint32_t b1) {
    asm volatile("mma.sync.aligned.m16n8k8.row.col.f32.tf32.tf32.f32 "
                 "{%0,%1,%2,%3}, {%4,%5,%6,%7}, {%8,%9}, {%0,%1,%2,%3};"
                 : "+f"(d[0]), "+f"(d[1]), "+f"(d[2]), "+f"(d[3])
                 : "r"(a0), "r"(a1), "r"(a2), "r"(a3), "r"(b0), "r"(b1));
}

#define AROW 68   // fp32/tf32 smem row stride (u32)

// ---------------- degree / CSR ----------------
__global__ void k_zero(int N) {
    int i = blockIdx.x * blockDim.x + threadIdx.x;
    if (i < N) g_degi[i] = 0;
}

__global__ void k_hist(const int* __restrict__ ei, int E) {
    int e = blockIdx.x * blockDim.x + threadIdx.x;
    if (e < E) {
        int d = ei[E + e];
        g_erank[e] = atomicAdd(&g_degi[d], 1);
    }
}

__global__ __launch_bounds__(SCAN_T) void k_scan_local(int N) {
    __shared__ int sdata[SCAN_T];
    int base = blockIdx.x * SCAN_ITEMS;
    int i0 = base + threadIdx.x * 2;
    int d0 = (i0     < N) ? g_degi[i0]     : 0;
    int d1 = (i0 + 1 < N) ? g_degi[i0 + 1] : 0;
    int tsum = d0 + d1;
    sdata[threadIdx.x] = tsum;
    __syncthreads();
    for (int off = 1; off < SCAN_T; off <<= 1) {
        int v = (threadIdx.x >= off) ? sdata[threadIdx.x - off] : 0;
        __syncthreads();
        sdata[threadIdx.x] += v;
        __syncthreads();
    }
    int excl = sdata[threadIdx.x] - tsum;
    if (i0     < N) g_rowptr[i0]     = excl;
    if (i0 + 1 < N) g_rowptr[i0 + 1] = excl + d0;
    if (threadIdx.x == SCAN_T - 1) g_bsum[blockIdx.x] = sdata[SCAN_T - 1];
}

__global__ __launch_bounds__(SCAN_T) void k_scan_bsums(int B) {
    __shared__ int sdata[SCAN_T];
    int v = (threadIdx.x < B) ? g_bsum[threadIdx.x] : 0;
    sdata[threadIdx.x] = v;
    __syncthreads();
    for (int off = 1; off < SCAN_T; off <<= 1) {
        int p = (threadIdx.x >= off) ? sdata[threadIdx.x - off] : 0;
        __syncthreads();
        sdata[threadIdx.x] += p;
        __syncthreads();
    }
    if (threadIdx.x < B) g_bsum[threadIdx.x] = sdata[threadIdx.x] - v;
}

__global__ void k_scan_add_prep(const float* __restrict__ x, int N, int E) {
    int i = blockIdx.x * blockDim.x + threadIdx.x;
    if (i == 0) g_rowptr[N] = E;
    if (i >= N) return;
    g_rowptr[i] += g_bsum[i / SCAN_ITEMS];
    float di = rsqrtf((float)(g_degi[i] + 1));
    g_dinv[i] = di;
    g_xs4[i] = make_float4(di * x[(size_t)i * 3 + 0],
                           di * x[(size_t)i * 3 + 1],
                           di * x[(size_t)i * 3 + 2], 0.0f);
}

__global__ void k_fill(const int* __restrict__ ei, int E) {
    int e = blockIdx.x * blockDim.x + threadIdx.x;
    if (e >= E) return;
    int s = ei[e];
    int d = ei[E + e];
    g_esrc[g_rowptr[d] + g_erank[e]] = s;
}

// ---------------- tf32 tensor-core GEMM phase ----------------
// sA is DESTROYED by the epilogue (sC overlays it after a sync).
__device__ __forceinline__ void gemm_mma(uint32_t* sA, const uint32_t* sB,
                                         const float* sdinv,
                                         __nv_bfloat16* outBuf, int nodeBase, int N) {
    int tid  = threadIdx.x;
    int w    = tid >> 5;
    int lane = tid & 31;
    int mw = w & 3;
    int nw = w >> 2;
    int g  = lane >> 2;
    int t  = lane & 3;

    float d[4][4];
    #pragma unroll
    for (int i = 0; i < 4; i++)
        #pragma unroll
        for (int j = 0; j < 4; j++) d[i][j] = 0.0f;

    const uint32_t* aRow0 = sA + (mw * 16 + g) * AROW;
    const uint32_t* aRow1 = aRow0 + 8 * AROW;
    int nbase = nw * 32 + g;

    #pragma unroll
    for (int kt = 0; kt < 8; kt++) {
        int k0 = kt * 8 + t;
        uint32_t a0 = aRow0[k0];
        uint32_t a1 = aRow1[k0];
        uint32_t a2 = aRow0[k0 + 4];
        uint32_t a3 = aRow1[k0 + 4];
        const uint32_t* b0p = sB + k0 * AROW + nbase;
        const uint32_t* b1p = b0p + 4 * AROW;
        #pragma unroll
        for (int nt = 0; nt < 4; nt++) {
            mma_tf32(d[nt], a0, a1, a2, a3, b0p[nt * 8], b1p[nt * 8]);
        }
    }

    // all warps finished reading sA -> safe to overlay epilogue staging
    __syncthreads();
    uint32_t* sC = sA;

    int r0 = mw * 16 + g;
    int r1 = r0 + 8;
    float di0 = sdinv[r0], di1 = sdinv[r1];
    #pragma unroll
    for (int nt = 0; nt < 4; nt++) {
        int cp = nw * 16 + nt * 4 + t;
        sC[r0 * 36 + cp] = pack_bf16x2(d[nt][0] * di0, d[nt][1] * di0);
        sC[r1 * 36 + cp] = pack_bf16x2(d[nt][2] * di1, d[nt][3] * di1);
    }
    __syncthreads();

    int r = tid >> 2, q = tid & 3;
    if (nodeBase + r < N) {
        uint4 v0 = *(uint4*)&sC[r * 36 + q * 8];
        uint4 v1 = *(uint4*)&sC[r * 36 + q * 8 + 4];
        __nv_bfloat16* o = outBuf + (size_t)(nodeBase + r) * HDIM + q * 16;
        *(uint4*)o       = v0;
        *((uint4*)o + 1) = v1;
    }
}

__device__ __forceinline__ void load_W_tf32(const float* __restrict__ W, uint32_t* sB) {
    int tid = threadIdx.x;
    #pragma unroll
    for (int i = tid; i < 1024; i += 256) {
        int k = i >> 4, cq = i & 15;
        float4 wv = ((const float4*)W)[i];
        uint32_t* o = sB + k * AROW + cq * 4;
        o[0] = f2tf32(wv.x); o[1] = f2tf32(wv.y);
        o[2] = f2tf32(wv.z); o[3] = f2tf32(wv.w);
    }
}

__device__ __forceinline__ void load_dinv(float* sdinv, int nodeBase, int N) {
    int tid = threadIdx.x;
    if (tid >= 64 && tid < 128) {
        int n = nodeBase + tid - 64;
        sdinv[tid - 64] = (n < N) ? g_dinv[n] : 0.0f;
    }
}

// ---------------- kA: fused x-aggregation + layer-1 + layer-2 transforms -> m0 ----------------
__global__ __launch_bounds__(256, 4) void kA_l12(const float* __restrict__ W1,
                                                 const float* __restrict__ b1,
                                                 const float* __restrict__ W2, int N) {
    __shared__ __align__(16) uint32_t sA[64 * AROW];
    __shared__ __align__(16) uint32_t sB[64 * AROW];
    __shared__ float4 sxa[64];
    __shared__ float sW1[192];
    __shared__ float sb1[64];
    __shared__ float sdinv[64];
    int tid = threadIdx.x;
    int nodeBase = blockIdx.x * 64;

    if (tid < 64) {
        int d = nodeBase + tid;
        float4 a = make_float4(0.f, 0.f, 0.f, 0.f);
        float di = 0.0f;
        if (d < N) {
            a = g_xs4[d];
            int i = g_rowptr[d], end = g_rowptr[d + 1];
            for (; i + 2 <= end; i += 2) {
                int s0 = g_esrc[i], s1 = g_esrc[i + 1];
                float4 v0 = g_xs4[s0];
                float4 v1 = g_xs4[s1];
                a.x += v0.x + v1.x; a.y += v0.y + v1.y; a.z += v0.z + v1.z;
            }
            if (i < end) {
                float4 v = g_xs4[g_esrc[i]];
                a.x += v.x; a.y += v.y; a.z += v.z;
            }
            di = g_dinv[d];
        }
        sxa[tid] = make_float4(di * a.x, di * a.y, di * a.z, 0.0f);
    }
    if (tid >= 192) {
        int j = tid - 192;
        if (j < 64) sb1[j] = b1[j];
    }
    if (tid >= 128 && tid < 192) {
        sW1[tid - 128] = W1[tid - 128];
        sW1[tid - 64]  = W1[tid - 64];
        sW1[tid]       = W1[tid];
    }
    load_dinv(sdinv, nodeBase, N);
    load_W_tf32(W2, sB);
    __syncthreads();

    #pragma unroll
    for (int i = tid; i < 4096; i += 256) {
        int n = i >> 6, c = i & 63;
        float4 xa = sxa[n];
        float v = sb1[c] + xa.x * sW1[c] + xa.y * sW1[64 + c] + xa.z * sW1[128 + c];
        sA[n * AROW + c] = f2tf32(fmaxf(v, 0.0f));
    }
    __syncthreads();

    gemm_mma(sA, sB, sdinv, g_m0, nodeBase, N);
}

// ---------------- kB: fused layer-2 aggregation + layer-3 transform -> m1 ----------------
__global__ __launch_bounds__(256, 4) void kB_agg_tr(const float* __restrict__ b2,
                                                    const float* __restrict__ W3, int N) {
    __shared__ __align__(16) uint32_t sA[64 * AROW];
    __shared__ __align__(16) uint32_t sB[64 * AROW];
    __shared__ float sb2[64];
    __shared__ float sdinv[64];
    int tid = threadIdx.x;
    int nodeBase = blockIdx.x * 64;

    if (tid < 64) sb2[tid] = b2[tid];
    load_dinv(sdinv, nodeBase, N);
    load_W_tf32(W3, sB);

    {
        int w    = tid >> 5;
        int lane = tid & 31;
        int oct  = lane >> 3;
        int l8   = lane & 7;
        #pragma unroll
        for (int j = 0; j < 2; j++) {
            int nl = w * 8 + j * 4 + oct;
            int d  = nodeBase + nl;
            float a[8] = {0.f, 0.f, 0.f, 0.f, 0.f, 0.f, 0.f, 0.f};
            float di = 0.0f;
            if (d < N) {
                acc_uint4(a, ((const uint4*)(g_m0 + (size_t)d * HDIM))[l8]);
                int i = g_rowptr[d], end = g_rowptr[d + 1];
                for (; i + 2 <= end; i += 2) {
                    int s0 = g_esrc[i], s1 = g_esrc[i + 1];
                    uint4 u0 = ((const uint4*)(g_m0 + (size_t)s0 * HDIM))[l8];
                    uint4 u1 = ((const uint4*)(g_m0 + (size_t)s1 * HDIM))[l8];
                    acc_uint4(a, u0);
                    acc_uint4(a, u1);
                }
                if (i < end) {
                    int s = g_esrc[i];
                    acc_uint4(a, ((const uint4*)(g_m0 + (size_t)s * HDIM))[l8]);
                }
                di = g_dinv[d];
            }
            const float* bb = &sb2[l8 * 8];
            uint32_t* o = sA + nl * AROW + l8 * 8;
            #pragma unroll
            for (int k = 0; k < 8; k++)
                o[k] = f2tf32(fmaxf(bb[k] + di * a[k], 0.f));
        }
    }
    __syncthreads();

    gemm_mma(sA, sB, sdinv, g_m1, nodeBase, N);
}

// ---------------- kC: fused layer-3 aggregation + relu + pool partials ----------------
__global__ __launch_bounds__(256) void kC_agg_pool(const float* __restrict__ b, int N) {
    int tid  = threadIdx.x;
    int w    = tid >> 5;
    int lane = tid & 31;
    int oct  = lane >> 3;
    int l8   = lane & 7;

    float bb[8];
    #pragma unroll
    for (int k = 0; k < 8; k++) bb[k] = b[l8 * 8 + k];
    float acc[8] = {0.f, 0.f, 0.f, 0.f, 0.f, 0.f, 0.f, 0.f};

    int stride = gridDim.x * 32;
    for (int d = blockIdx.x * 32 + w * 4 + oct; d < N; d += stride) {
        float a[8] = {0.f, 0.f, 0.f, 0.f, 0.f, 0.f, 0.f, 0.f};
        acc_uint4(a, ((const uint4*)(g_m1 + (size_t)d * HDIM))[l8]);
        int i = g_rowptr[d], end = g_rowptr[d + 1];
        for (; i + 2 <= end; i += 2) {
            int s0 = g_esrc[i], s1 = g_esrc[i + 1];
            uint4 u0 = ((const uint4*)(g_m1 + (size_t)s0 * HDIM))[l8];
            uint4 u1 = ((const uint4*)(g_m1 + (size_t)s1 * HDIM))[l8];
            acc_uint4(a, u0);
            acc_uint4(a, u1);
        }
        if (i < end) {
            int s = g_esrc[i];
            acc_uint4(a, ((const uint4*)(g_m1 + (size_t)s * HDIM))[l8]);
        }
        float di = g_dinv[d];
        #pragma unroll
        for (int k = 0; k < 8; k++)
            acc[k] += fmaxf(bb[k] + di * a[k], 0.f);
    }

    __shared__ float sp[64];
    if (tid < 64) sp[tid] = 0.0f;
    __syncthreads();
    #pragma unroll
    for (int k = 0; k < 8; k++)
        atomicAdd(&sp[l8 * 8 + k], acc[k]);
    __syncthreads();
    if (tid < 64) g_partial[(size_t)blockIdx.x * HDIM + tid] = sp[tid];
}

__global__ __launch_bounds__(256) void k_reduce(int numPartial) {
    __shared__ float sdata[256];
    int c = blockIdx.x;
    float s = 0.0f;
    for (int i = threadIdx.x; i < numPartial; i += 256)
        s += g_partial[(size_t)i * HDIM + c];
    sdata[threadIdx.x] = s;
    __syncthreads();
    for (int off = 128; off > 0; off >>= 1) {
        if (threadIdx.x < off) sdata[threadIdx.x] += sdata[threadIdx.x + off];
        __syncthreads();
    }
    if (threadIdx.x == 0) g_pool[c] = sdata[0];
}

__global__ void k_final(const float* __restrict__ Wfc, const float* __restrict__ bfc,
                        float* __restrict__ out, int N) {
    int c = threadIdx.x;
    if (c >= 24) return;
    float invN = 1.0f / (float)N;
    float acc = bfc[c];
    #pragma unroll
    for (int k = 0; k < 64; k++)
        acc += (g_pool[k] * invN) * Wfc[k * 24 + c];
    out[c] = tanhf(acc);
}

// ---------------- launch ----------------
extern "C" void kernel_launch(void* const* d_in, const int* in_sizes, int n_in,
                              void* d_out, int out_size) {
    const float* x   = (const float*)d_in[0];
    const int*   ei  = (const int*)d_in[1];   // int32 (JAX x64 disabled)
    const float* W1  = (const float*)d_in[3];
    const float* b1  = (const float*)d_in[4];
    const float* W2  = (const float*)d_in[5];
    const float* b2  = (const float*)d_in[6];
    const float* W3  = (const float*)d_in[7];
    const float* b3  = (const float*)d_in[8];
    const float* Wfc = (const float*)d_in[9];
    const float* bfc = (const float*)d_in[10];
    float* out = (float*)d_out;

    int N = in_sizes[0] / 3;
    int E = in_sizes[1] / 2;

    const int T = 256;
    int nbN    = (N + T - 1) / T;
    int nbE    = (E + T - 1) / T;
    int nbTr   = (N + 63) / 64;
    int nbScan = (N + SCAN_ITEMS - 1) / SCAN_ITEMS;

    // CSR + normalization
    k_zero<<<nbN, T>>>(N);
    k_hist<<<nbE, T>>>(ei, E);
    k_scan_local<<<nbScan, SCAN_T>>>(N);
    k_scan_bsums<<<1, SCAN_T>>>(nbScan);
    k_scan_add_prep<<<nbN, T>>>(x, N, E);
    k_fill<<<nbE, T>>>(ei, E);

    // fused x-agg + layer1 + layer2 transforms -> m0 (tf32 tensor cores)
    kA_l12<<<nbTr, T>>>(W1, b1, W2, N);

    // fused layer2 aggregation + layer3 transform -> m1 (tf32 tensor cores)
    kB_agg_tr<<<nbTr, T>>>(b2, W3, N);

    // fused layer3 aggregation + relu + mean-pool
    kC_agg_pool<<<POOL_BLOCKS, T>>>(b3, N);

    // reduce + FC + tanh
    k_reduce<<<64, 256>>>(POOL_BLOCKS);
    k_final<<<1, 32>>>(Wfc, bfc, out, N);
}

// round 16
// speedup vs baseline: 1.0132x; 1.0132x over previous
#include <cuda_runtime.h>
#include <cuda_bf16.h>
#include <cstdint>
#include <math.h>

#define MAX_N 500000
#define MAX_E 1000000
#define HDIM  64
#define SCAN_T 512
#define SCAN_ITEMS 1024
#define POOL_BLOCKS 2960

// ---------------- device scratch ----------------
__device__ __nv_bfloat16 g_m0[(size_t)MAX_N * HDIM];  // layer-2 messages (bf16)
__device__ __nv_bfloat16 g_m1[(size_t)MAX_N * HDIM];  // layer-3 messages (bf16)
__device__ float g_dinv[MAX_N];
__device__ float4 g_xs4[MAX_N];
__device__ int   g_degi[MAX_N];
__device__ int   g_rowptr[MAX_N + 1];
__device__ int   g_erank[MAX_E];
__device__ int   g_esrc[MAX_E];
__device__ int   g_bsum[1024];
__device__ float g_partial[(size_t)POOL_BLOCKS * HDIM];
__device__ float g_pool[HDIM];

// ---------------- helpers ----------------
__device__ __forceinline__ unsigned pack_bf16x2(float lo, float hi) {
    unsigned r;
    asm("cvt.rn.bf16x2.f32 %0, %1, %2;" : "=r"(r) : "f"(hi), "f"(lo));
    return r;
}
__device__ __forceinline__ void acc_bf16x2(float& a0, float& a1, unsigned v) {
    __nv_bfloat162 b = *reinterpret_cast<__nv_bfloat162*>(&v);
    float2 f = __bfloat1622float2(b);
    a0 += f.x; a1 += f.y;
}
__device__ __forceinline__ void acc_uint4(float* a, uint4 v) {
    acc_bf16x2(a[0], a[1], v.x);
    acc_bf16x2(a[2], a[3], v.y);
    acc_bf16x2(a[4], a[5], v.z);
    acc_bf16x2(a[6], a[7], v.w);
}
__device__ __forceinline__ uint32_t f2tf32(float f) {
    uint32_t r;
    asm("cvt.rna.tf32.f32 %0, %1;" : "=r"(r) : "f"(f));
    return r;
}
__device__ __forceinline__ void mma_tf32(float* d, uint32_t a0, uint32_t a1, uint32_t a2,
                                         uint32_t a3, uint32_t b0, uint32_t b1) {
    asm volatile("mma.sync.aligned.m16n8k8.row.col.f32.tf32.tf32.f32 "
                 "{%0,%1,%2,%3}, {%4,%5,%6,%7}, {%8,%9}, {%0,%1,%2,%3};"
                 : "+f"(d[0]), "+f"(d[1]), "+f"(d[2]), "+f"(d[3])
                 : "r"(a0), "r"(a1), "r"(a2), "r"(a3), "r"(b0), "r"(b1));
}

#define AROW 68   // fp32/tf32 smem row stride (u32)

// ---------------- degree / CSR ----------------
__global__ void k_zero(int N) {
    int i = blockIdx.x * blockDim.x + threadIdx.x;
    if (i < N) g_degi[i] = 0;
}

__global__ void k_hist(const int* __restrict__ ei, int E) {
    int e = blockIdx.x * blockDim.x + threadIdx.x;
    if (e < E) {
        int d = ei[E + e];
        g_erank[e] = atomicAdd(&g_degi[d], 1);
    }
}

__global__ __launch_bounds__(SCAN_T) void k_scan_local(int N) {
    __shared__ int sdata[SCAN_T];
    int base = blockIdx.x * SCAN_ITEMS;
    int i0 = base + threadIdx.x * 2;
    int d0 = (i0     < N) ? g_degi[i0]     : 0;
    int d1 = (i0 + 1 < N) ? g_degi[i0 + 1] : 0;
    int tsum = d0 + d1;
    sdata[threadIdx.x] = tsum;
    __syncthreads();
    for (int off = 1; off < SCAN_T; off <<= 1) {
        int v = (threadIdx.x >= off) ? sdata[threadIdx.x - off] : 0;
        __syncthreads();
        sdata[threadIdx.x] += v;
        __syncthreads();
    }
    int excl = sdata[threadIdx.x] - tsum;
    if (i0     < N) g_rowptr[i0]     = excl;
    if (i0 + 1 < N) g_rowptr[i0 + 1] = excl + d0;
    if (threadIdx.x == SCAN_T - 1) g_bsum[blockIdx.x] = sdata[SCAN_T - 1];
}

__global__ __launch_bounds__(SCAN_T) void k_scan_bsums(int B) {
    __shared__ int sdata[SCAN_T];
    int v = (threadIdx.x < B) ? g_bsum[threadIdx.x] : 0;
    sdata[threadIdx.x] = v;
    __syncthreads();
    for (int off = 1; off < SCAN_T; off <<= 1) {
        int p = (threadIdx.x >= off) ? sdata[threadIdx.x - off] : 0;
        __syncthreads();
        sdata[threadIdx.x] += p;
        __syncthreads();
    }
    if (threadIdx.x < B) g_bsum[threadIdx.x] = sdata[threadIdx.x] - v;
}

__global__ void k_scan_add_prep(const float* __restrict__ x, int N, int E) {
    int i = blockIdx.x * blockDim.x + threadIdx.x;
    if (i == 0) g_rowptr[N] = E;
    if (i >= N) return;
    g_rowptr[i] += g_bsum[i / SCAN_ITEMS];
    float di = rsqrtf((float)(g_degi[i] + 1));
    g_dinv[i] = di;
    g_xs4[i] = make_float4(di * x[(size_t)i * 3 + 0],
                           di * x[(size_t)i * 3 + 1],
                           di * x[(size_t)i * 3 + 2], 0.0f);
}

__global__ void k_fill(const int* __restrict__ ei, int E) {
    int e = blockIdx.x * blockDim.x + threadIdx.x;
    if (e >= E) return;
    int s = ei[e];
    int d = ei[E + e];
    g_esrc[g_rowptr[d] + g_erank[e]] = s;
}

// ---------------- tf32 tensor-core GEMM phase ----------------
__device__ __forceinline__ void gemm_mma(const uint32_t* sA, const uint32_t* sB,
                                         uint32_t* sC, const float* sdinv,
                                         __nv_bfloat16* outBuf, int nodeBase, int N) {
    int tid  = threadIdx.x;
    int w    = tid >> 5;
    int lane = tid & 31;
    int mw = w & 3;
    int nw = w >> 2;
    int g  = lane >> 2;
    int t  = lane & 3;

    float d[4][4];
    #pragma unroll
    for (int i = 0; i < 4; i++)
        #pragma unroll
        for (int j = 0; j < 4; j++) d[i][j] = 0.0f;

    const uint32_t* aRow0 = sA + (mw * 16 + g) * AROW;
    const uint32_t* aRow1 = aRow0 + 8 * AROW;
    int nbase = nw * 32 + g;

    #pragma unroll
    for (int kt = 0; kt < 8; kt++) {
        int k0 = kt * 8 + t;
        uint32_t a0 = aRow0[k0];
        uint32_t a1 = aRow1[k0];
        uint32_t a2 = aRow0[k0 + 4];
        uint32_t a3 = aRow1[k0 + 4];
        const uint32_t* b0p = sB + k0 * AROW + nbase;
        const uint32_t* b1p = b0p + 4 * AROW;
        #pragma unroll
        for (int nt = 0; nt < 4; nt++) {
            mma_tf32(d[nt], a0, a1, a2, a3, b0p[nt * 8], b1p[nt * 8]);
        }
    }

    int r0 = mw * 16 + g;
    int r1 = r0 + 8;
    float di0 = sdinv[r0], di1 = sdinv[r1];
    #pragma unroll
    for (int nt = 0; nt < 4; nt++) {
        int cp = nw * 16 + nt * 4 + t;
        sC[r0 * 36 + cp] = pack_bf16x2(d[nt][0] * di0, d[nt][1] * di0);
        sC[r1 * 36 + cp] = pack_bf16x2(d[nt][2] * di1, d[nt][3] * di1);
    }
    __syncthreads();

    int r = tid >> 2, q = tid & 3;
    if (nodeBase + r < N) {
        uint4 v0 = *(uint4*)&sC[r * 36 + q * 8];
        uint4 v1 = *(uint4*)&sC[r * 36 + q * 8 + 4];
        __nv_bfloat16* o = outBuf + (size_t)(nodeBase + r) * HDIM + q * 16;
        *(uint4*)o       = v0;
        *((uint4*)o + 1) = v1;
    }
}

__device__ __forceinline__ void load_W_tf32(const float* __restrict__ W, uint32_t* sB) {
    int tid = threadIdx.x;
    #pragma unroll
    for (int i = tid; i < 1024; i += 256) {
        int k = i >> 4, cq = i & 15;
        float4 wv = ((const float4*)W)[i];
        uint32_t* o = sB + k * AROW + cq * 4;
        o[0] = f2tf32(wv.x); o[1] = f2tf32(wv.y);
        o[2] = f2tf32(wv.z); o[3] = f2tf32(wv.w);
    }
}

__device__ __forceinline__ void load_dinv(float* sdinv, int nodeBase, int N) {
    int tid = threadIdx.x;
    if (tid >= 64 && tid < 128) {
        int n = nodeBase + tid - 64;
        sdinv[tid - 64] = (n < N) ? g_dinv[n] : 0.0f;
    }
}

// ---------------- kA: fused x-aggregation + layer-1 + layer-2 transforms -> m0 ----------------
__global__ __launch_bounds__(256) void kA_l12(const float* __restrict__ W1,
                                              const float* __restrict__ b1,
                                              const float* __restrict__ W2, int N) {
    __shared__ __align__(16) uint32_t sA[64 * AROW];
    __shared__ __align__(16) uint32_t sB[64 * AROW];
    __shared__ __align__(16) uint32_t sC[64 * 36];
    __shared__ float4 sxa[64];
    __shared__ float sW1[192];
    __shared__ float sb1[64];
    __shared__ float sdinv[64];
    int tid = threadIdx.x;
    int nodeBase = blockIdx.x * 64;

    if (tid < 64) {
        int d = nodeBase + tid;
        float4 a = make_float4(0.f, 0.f, 0.f, 0.f);
        float di = 0.0f;
        if (d < N) {
            a = g_xs4[d];
            int i = g_rowptr[d], end = g_rowptr[d + 1];
            for (; i + 2 <= end; i += 2) {
                int s0 = g_esrc[i], s1 = g_esrc[i + 1];
                float4 v0 = g_xs4[s0];
                float4 v1 = g_xs4[s1];
                a.x += v0.x + v1.x; a.y += v0.y + v1.y; a.z += v0.z + v1.z;
            }
            if (i < end) {
                float4 v = g_xs4[g_esrc[i]];
                a.x += v.x; a.y += v.y; a.z += v.z;
            }
            di = g_dinv[d];
        }
        sxa[tid] = make_float4(di * a.x, di * a.y, di * a.z, 0.0f);
    }
    if (tid >= 192) {
        int j = tid - 192;
        if (j < 64) sb1[j] = b1[j];
    }
    if (tid >= 128 && tid < 192) {
        sW1[tid - 128] = W1[tid - 128];
        sW1[tid - 64]  = W1[tid - 64];
        sW1[tid]       = W1[tid];
    }
    load_dinv(sdinv, nodeBase, N);
    load_W_tf32(W2, sB);
    __syncthreads();

    #pragma unroll
    for (int i = tid; i < 4096; i += 256) {
        int n = i >> 6, c = i & 63;
        float4 xa = sxa[n];
        float v = sb1[c] + xa.x * sW1[c] + xa.y * sW1[64 + c] + xa.z * sW1[128 + c];
        sA[n * AROW + c] = f2tf32(fmaxf(v, 0.0f));
    }
    __syncthreads();

    gemm_mma(sA, sB, sC, sdinv, g_m0, nodeBase, N);
}

// ---------------- kB: fused layer-2 aggregation + layer-3 transform -> m1 ----------------
// Gather remapped so warp pair {p, p+4} produces exactly A-tile rows p*16..p*16+15;
// pair-scoped named barrier lets fast pairs start their mma while slow pairs gather.
__global__ __launch_bounds__(256) void kB_agg_tr(const float* __restrict__ b2,
                                                 const float* __restrict__ W3, int N) {
    __shared__ __align__(16) uint32_t sA[64 * AROW];
    __shared__ __align__(16) uint32_t sB[64 * AROW];
    __shared__ __align__(16) uint32_t sC[64 * 36];
    __shared__ float sb2[64];
    __shared__ float sdinv[64];
    int tid = threadIdx.x;
    int nodeBase = blockIdx.x * 64;

    if (tid < 64) sb2[tid] = b2[tid];
    load_dinv(sdinv, nodeBase, N);
    load_W_tf32(W3, sB);
    __syncthreads();   // uniform-cost: sB/sb2/sdinv visible to all before gather

    {
        int w    = tid >> 5;
        int p    = w & 3;          // pair id = mma A-tile index (mw)
        int h    = w >> 2;         // half-of-pair = nw
        int lane = tid & 31;
        int oct  = lane >> 3;
        int l8   = lane & 7;
        #pragma unroll
        for (int j = 0; j < 2; j++) {
            int nl = p * 16 + h * 8 + j * 4 + oct;   // pair p covers rows p*16..p*16+15
            int d  = nodeBase + nl;
            float a[8] = {0.f, 0.f, 0.f, 0.f, 0.f, 0.f, 0.f, 0.f};
            float di = 0.0f;
            if (d < N) {
                acc_uint4(a, ((const uint4*)(g_m0 + (size_t)d * HDIM))[l8]);
                int i = g_rowptr[d], end = g_rowptr[d + 1];
                for (; i + 2 <= end; i += 2) {
                    int s0 = g_esrc[i], s1 = g_esrc[i + 1];
                    uint4 u0 = ((const uint4*)(g_m0 + (size_t)s0 * HDIM))[l8];
                    uint4 u1 = ((const uint4*)(g_m0 + (size_t)s1 * HDIM))[l8];
                    acc_uint4(a, u0);
                    acc_uint4(a, u1);
                }
                if (i < end) {
                    int s = g_esrc[i];
                    acc_uint4(a, ((const uint4*)(g_m0 + (size_t)s * HDIM))[l8]);
                }
                di = g_dinv[d];
            }
            const float* bb = &sb2[l8 * 8];
            uint32_t* o = sA + nl * AROW + l8 * 8;
            #pragma unroll
            for (int k = 0; k < 8; k++)
                o[k] = f2tf32(fmaxf(bb[k] + di * a[k], 0.f));
        }
        // pair-scoped barrier: warps p and p+4 (64 threads) sync on named barrier p+1
        asm volatile("bar.sync %0, 64;" :: "r"(p + 1) : "memory");
    }

    gemm_mma(sA, sB, sC, sdinv, g_m1, nodeBase, N);
}

// ---------------- kC: fused layer-3 aggregation + relu + pool partials ----------------
__global__ __launch_bounds__(256) void kC_agg_pool(const float* __restrict__ b, int N) {
    int tid  = threadIdx.x;
    int w    = tid >> 5;
    int lane = tid & 31;
    int oct  = lane >> 3;
    int l8   = lane & 7;

    float bb[8];
    #pragma unroll
    for (int k = 0; k < 8; k++) bb[k] = b[l8 * 8 + k];
    float acc[8] = {0.f, 0.f, 0.f, 0.f, 0.f, 0.f, 0.f, 0.f};

    int stride = gridDim.x * 32;
    for (int d = blockIdx.x * 32 + w * 4 + oct; d < N; d += stride) {
        float a[8] = {0.f, 0.f, 0.f, 0.f, 0.f, 0.f, 0.f, 0.f};
        acc_uint4(a, ((const uint4*)(g_m1 + (size_t)d * HDIM))[l8]);
        int i = g_rowptr[d], end = g_rowptr[d + 1];
        for (; i + 2 <= end; i += 2) {
            int s0 = g_esrc[i], s1 = g_esrc[i + 1];
            uint4 u0 = ((const uint4*)(g_m1 + (size_t)s0 * HDIM))[l8];
            uint4 u1 = ((const uint4*)(g_m1 + (size_t)s1 * HDIM))[l8];
            acc_uint4(a, u0);
            acc_uint4(a, u1);
        }
        if (i < end) {
            int s = g_esrc[i];
            acc_uint4(a, ((const uint4*)(g_m1 + (size_t)s * HDIM))[l8]);
        }
        float di = g_dinv[d];
        #pragma unroll
        for (int k = 0; k < 8; k++)
            acc[k] += fmaxf(bb[k] + di * a[k], 0.f);
    }

    __shared__ float sp[64];
    if (tid < 64) sp[tid] = 0.0f;
    __syncthreads();
    #pragma unroll
    for (int k = 0; k < 8; k++)
        atomicAdd(&sp[l8 * 8 + k], acc[k]);
    __syncthreads();
    if (tid < 64) g_partial[(size_t)blockIdx.x * HDIM + tid] = sp[tid];
}

__global__ __launch_bounds__(256) void k_reduce(int numPartial) {
    __shared__ float sdata[256];
    int c = blockIdx.x;
    float s = 0.0f;
    for (int i = threadIdx.x; i < numPartial; i += 256)
        s += g_partial[(size_t)i * HDIM + c];
    sdata[threadIdx.x] = s;
    __syncthreads();
    for (int off = 128; off > 0; off >>= 1) {
        if (threadIdx.x < off) sdata[threadIdx.x] += sdata[threadIdx.x + off];
        __syncthreads();
    }
    if (threadIdx.x == 0) g_pool[c] = sdata[0];
}

__global__ void k_final(const float* __restrict__ Wfc, const float* __restrict__ bfc,
                        float* __restrict__ out, int N) {
    int c = threadIdx.x;
    if (c >= 24) return;
    float invN = 1.0f / (float)N;
    float acc = bfc[c];
    #pragma unroll
    for (int k = 0; k < 64; k++)
        acc += (g_pool[k] * invN) * Wfc[k * 24 + c];
    out[c] = tanhf(acc);
}

// ---------------- launch ----------------
extern "C" void kernel_launch(void* const* d_in, const int* in_sizes, int n_in,
                              void* d_out, int out_size) {
    const float* x   = (const float*)d_in[0];
    const int*   ei  = (const int*)d_in[1];   // int32 (JAX x64 disabled)
    const float* W1  = (const float*)d_in[3];
    const float* b1  = (const float*)d_in[4];
    const float* W2  = (const float*)d_in[5];
    const float* b2  = (const float*)d_in[6];
    const float* W3  = (const float*)d_in[7];
    const float* b3  = (const float*)d_in[8];
    const float* Wfc = (const float*)d_in[9];
    const float* bfc = (const float*)d_in[10];
    float* out = (float*)d_out;

    int N = in_sizes[0] / 3;
    int E = in_sizes[1] / 2;

    const int T = 256;
    int nbN    = (N + T - 1) / T;
    int nbE    = (E + T - 1) / T;
    int nbTr   = (N + 63) / 64;
    int nbScan = (N + SCAN_ITEMS - 1) / SCAN_ITEMS;

    // CSR + normalization
    k_zero<<<nbN, T>>>(N);
    k_hist<<<nbE, T>>>(ei, E);
    k_scan_local<<<nbScan, SCAN_T>>>(N);
    k_scan_bsums<<<1, SCAN_T>>>(nbScan);
    k_scan_add_prep<<<nbN, T>>>(x, N, E);
    k_fill<<<nbE, T>>>(ei, E);

    // fused x-agg + layer1 + layer2 transforms -> m0 (tf32 tensor cores)
    kA_l12<<<nbTr, T>>>(W1, b1, W2, N);

    // fused layer2 aggregation + layer3 transform -> m1 (pair-barrier overlap)
    kB_agg_tr<<<nbTr, T>>>(b2, W3, N);

    // fused layer3 aggregation + relu + mean-pool
    kC_agg_pool<<<POOL_BLOCKS, T>>>(b3, N);

    // reduce + FC + tanh
    k_reduce<<<64, 256>>>(POOL_BLOCKS);
    k_final<<<1, 32>>>(Wfc, bfc, out, N);
}

// round 17
// speedup vs baseline: 1.0346x; 1.0212x over previous
#include <cuda_runtime.h>
#include <cuda_bf16.h>
#include <cstdint>
#include <math.h>

#define MAX_N 500000
#define MAX_E 1000000
#define HDIM  64
#define SCAN_T 512
#define SCAN_ITEMS 1024
#define POOL_BLOCKS 2960

// ---------------- device scratch ----------------
__device__ __nv_bfloat16 g_m0[(size_t)MAX_N * HDIM];  // layer-2 messages (bf16)
__device__ __nv_bfloat16 g_m1[(size_t)MAX_N * HDIM];  // layer-3 messages (bf16)
__device__ float g_dinv[MAX_N];
__device__ float4 g_xs4[MAX_N];
__device__ int   g_degi[MAX_N];
__device__ int   g_rowptr[MAX_N + 1];
__device__ int   g_erank[MAX_E];
__device__ int   g_esrc[MAX_E];
__device__ int   g_bsum[1024];
__device__ float g_partial[(size_t)POOL_BLOCKS * HDIM];
__device__ float g_pool[HDIM];

// ---------------- helpers ----------------
__device__ __forceinline__ unsigned pack_bf16x2(float lo, float hi) {
    unsigned r;
    asm("cvt.rn.bf16x2.f32 %0, %1, %2;" : "=r"(r) : "f"(hi), "f"(lo));
    return r;
}
__device__ __forceinline__ void acc_bf16x2(float& a0, float& a1, unsigned v) {
    __nv_bfloat162 b = *reinterpret_cast<__nv_bfloat162*>(&v);
    float2 f = __bfloat1622float2(b);
    a0 += f.x; a1 += f.y;
}
__device__ __forceinline__ void acc_uint4(float* a, uint4 v) {
    acc_bf16x2(a[0], a[1], v.x);
    acc_bf16x2(a[2], a[3], v.y);
    acc_bf16x2(a[4], a[5], v.z);
    acc_bf16x2(a[6], a[7], v.w);
}
__device__ __forceinline__ uint32_t f2tf32(float f) {
    uint32_t r;
    asm("cvt.rna.tf32.f32 %0, %1;" : "=r"(r) : "f"(f));
    return r;
}
__device__ __forceinline__ void mma_tf32(float* d, uint32_t a0, uint32_t a1, uint32_t a2,
                                         uint32_t a3, uint32_t b0, uint32_t b1) {
    asm volatile("mma.sync.aligned.m16n8k8.row.col.f32.tf32.tf32.f32 "
                 "{%0,%1,%2,%3}, {%4,%5,%6,%7}, {%8,%9}, {%0,%1,%2,%3};"
                 : "+f"(d[0]), "+f"(d[1]), "+f"(d[2]), "+f"(d[3])
                 : "r"(a0), "r"(a1), "r"(a2), "r"(a3), "r"(b0), "r"(b1));
}

#define AROW 68   // fp32/tf32 smem row stride (u32)
#define TILE 128  // nodes per kA/kB block

// ---------------- degree / CSR ----------------
__global__ void k_zero(int N) {
    int i = blockIdx.x * blockDim.x + threadIdx.x;
    if (i < N) g_degi[i] = 0;
}

__global__ void k_hist(const int* __restrict__ ei, int E) {
    int e = blockIdx.x * blockDim.x + threadIdx.x;
    if (e < E) {
        int d = ei[E + e];
        g_erank[e] = atomicAdd(&g_degi[d], 1);
    }
}

__global__ __launch_bounds__(SCAN_T) void k_scan_local(int N) {
    __shared__ int sdata[SCAN_T];
    int base = blockIdx.x * SCAN_ITEMS;
    int i0 = base + threadIdx.x * 2;
    int d0 = (i0     < N) ? g_degi[i0]     : 0;
    int d1 = (i0 + 1 < N) ? g_degi[i0 + 1] : 0;
    int tsum = d0 + d1;
    sdata[threadIdx.x] = tsum;
    __syncthreads();
    for (int off = 1; off < SCAN_T; off <<= 1) {
        int v = (threadIdx.x >= off) ? sdata[threadIdx.x - off] : 0;
        __syncthreads();
        sdata[threadIdx.x] += v;
        __syncthreads();
    }
    int excl = sdata[threadIdx.x] - tsum;
    if (i0     < N) g_rowptr[i0]     = excl;
    if (i0 + 1 < N) g_rowptr[i0 + 1] = excl + d0;
    if (threadIdx.x == SCAN_T - 1) g_bsum[blockIdx.x] = sdata[SCAN_T - 1];
}

__global__ __launch_bounds__(SCAN_T) void k_scan_bsums(int B) {
    __shared__ int sdata[SCAN_T];
    int v = (threadIdx.x < B) ? g_bsum[threadIdx.x] : 0;
    sdata[threadIdx.x] = v;
    __syncthreads();
    for (int off = 1; off < SCAN_T; off <<= 1) {
        int p = (threadIdx.x >= off) ? sdata[threadIdx.x - off] : 0;
        __syncthreads();
        sdata[threadIdx.x] += p;
        __syncthreads();
    }
    if (threadIdx.x < B) g_bsum[threadIdx.x] = sdata[threadIdx.x] - v;
}

__global__ void k_scan_add_prep(const float* __restrict__ x, int N, int E) {
    int i = blockIdx.x * blockDim.x + threadIdx.x;
    if (i == 0) g_rowptr[N] = E;
    if (i >= N) return;
    g_rowptr[i] += g_bsum[i / SCAN_ITEMS];
    float di = rsqrtf((float)(g_degi[i] + 1));
    g_dinv[i] = di;
    g_xs4[i] = make_float4(di * x[(size_t)i * 3 + 0],
                           di * x[(size_t)i * 3 + 1],
                           di * x[(size_t)i * 3 + 2], 0.0f);
}

__global__ void k_fill(const int* __restrict__ ei, int E) {
    int e = blockIdx.x * blockDim.x + threadIdx.x;
    if (e >= E) return;
    int s = ei[e];
    int d = ei[E + e];
    g_esrc[g_rowptr[d] + g_erank[e]] = s;
}

// ---------------- tf32 tensor-core GEMM phase (128-node tile) ----------------
// warp w owns M16 tile w (rows w*16..w*16+15) x full N64.
// sA (128 x AROW u32) is DESTROYED: epilogue staging sC overlays it after a sync.
__device__ __forceinline__ void gemm_mma128(uint32_t* sA, const uint32_t* sB,
                                            const float* sdinv,
                                            __nv_bfloat16* outBuf, int nodeBase, int N) {
    int tid  = threadIdx.x;
    int w    = tid >> 5;
    int lane = tid & 31;
    int g  = lane >> 2;
    int t  = lane & 3;

    float d[8][4];
    #pragma unroll
    for (int i = 0; i < 8; i++)
        #pragma unroll
        for (int j = 0; j < 4; j++) d[i][j] = 0.0f;

    const uint32_t* aRow0 = sA + (w * 16 + g) * AROW;
    const uint32_t* aRow1 = aRow0 + 8 * AROW;

    #pragma unroll
    for (int kt = 0; kt < 8; kt++) {
        int k0 = kt * 8 + t;
        uint32_t a0 = aRow0[k0];
        uint32_t a1 = aRow1[k0];
        uint32_t a2 = aRow0[k0 + 4];
        uint32_t a3 = aRow1[k0 + 4];
        const uint32_t* b0p = sB + k0 * AROW + g;
        const uint32_t* b1p = b0p + 4 * AROW;
        #pragma unroll
        for (int nt = 0; nt < 8; nt++) {
            mma_tf32(d[nt], a0, a1, a2, a3, b0p[nt * 8], b1p[nt * 8]);
        }
    }

    // all warps done reading sA -> overlay epilogue staging
    __syncthreads();
    uint32_t* sC = sA;   // needs 128*36 u32 = 18.4 KB < 34.8 KB

    int r0 = w * 16 + g;
    int r1 = r0 + 8;
    float di0 = sdinv[r0], di1 = sdinv[r1];
    #pragma unroll
    for (int nt = 0; nt < 8; nt++) {
        int cp = nt * 4 + t;
        sC[r0 * 36 + cp] = pack_bf16x2(d[nt][0] * di0, d[nt][1] * di0);
        sC[r1 * 36 + cp] = pack_bf16x2(d[nt][2] * di1, d[nt][3] * di1);
    }
    __syncthreads();

    int r = tid >> 1, q = tid & 1;   // 2 threads per row, 4 uint4 each
    if (nodeBase + r < N) {
        const uint4* src = (const uint4*)&sC[r * 36 + q * 16];
        uint4* o = (uint4*)(outBuf + (size_t)(nodeBase + r) * HDIM + q * 32);
        o[0] = src[0]; o[1] = src[1]; o[2] = src[2]; o[3] = src[3];
    }
}

__device__ __forceinline__ void load_W_tf32(const float* __restrict__ W, uint32_t* sB) {
    int tid = threadIdx.x;
    #pragma unroll
    for (int i = tid; i < 1024; i += 256) {
        int k = i >> 4, cq = i & 15;
        float4 wv = ((const float4*)W)[i];
        uint32_t* o = sB + k * AROW + cq * 4;
        o[0] = f2tf32(wv.x); o[1] = f2tf32(wv.y);
        o[2] = f2tf32(wv.z); o[3] = f2tf32(wv.w);
    }
}

// ---------------- kA: fused x-aggregation + layer-1 + layer-2 transforms -> m0 ----------------
__global__ __launch_bounds__(256) void kA_l12(const float* __restrict__ W1,
                                              const float* __restrict__ b1,
                                              const float* __restrict__ W2, int N) {
    __shared__ __align__(16) uint32_t sA[TILE * AROW];   // 34.8 KB (reused as sC)
    __shared__ __align__(16) uint32_t sB[64 * AROW];     // 17.4 KB
    __shared__ float4 sxa[TILE];
    __shared__ float sW1[192];
    __shared__ float sb1[64];
    __shared__ float sdinv[TILE];
    int tid = threadIdx.x;
    int nodeBase = blockIdx.x * TILE;

    // threads 0..127: aggregate x for own node + stash dinv
    if (tid < TILE) {
        int d = nodeBase + tid;
        float4 a = make_float4(0.f, 0.f, 0.f, 0.f);
        float di = 0.0f;
        if (d < N) {
            a = g_xs4[d];
            int i = g_rowptr[d], end = g_rowptr[d + 1];
            for (; i + 2 <= end; i += 2) {
                int s0 = g_esrc[i], s1 = g_esrc[i + 1];
                float4 v0 = g_xs4[s0];
                float4 v1 = g_xs4[s1];
                a.x += v0.x + v1.x; a.y += v0.y + v1.y; a.z += v0.z + v1.z;
            }
            if (i < end) {
                float4 v = g_xs4[g_esrc[i]];
                a.x += v.x; a.y += v.y; a.z += v.z;
            }
            di = g_dinv[d];
        }
        sxa[tid] = make_float4(di * a.x, di * a.y, di * a.z, 0.0f);
        sdinv[tid] = di;
    }
    if (tid >= 128 && tid < 192) {
        int j = tid - 128;
        sW1[j]       = W1[j];
        sW1[j + 64]  = W1[j + 64];
        sW1[j + 128] = W1[j + 128];
    }
    if (tid >= 192) sb1[tid - 192] = b1[tid - 192];
    load_W_tf32(W2, sB);
    __syncthreads();

    // phase 1: sA[n][c] = tf32(relu(xa @ W1 + b1)), 128x64
    #pragma unroll
    for (int i = tid; i < TILE * 64; i += 256) {
        int n = i >> 6, c = i & 63;
        float4 xa = sxa[n];
        float v = sb1[c] + xa.x * sW1[c] + xa.y * sW1[64 + c] + xa.z * sW1[128 + c];
        sA[n * AROW + c] = f2tf32(fmaxf(v, 0.0f));
    }
    __syncthreads();

    gemm_mma128(sA, sB, sdinv, g_m0, nodeBase, N);
}

// ---------------- kB: fused layer-2 aggregation + layer-3 transform -> m1 ----------------
__global__ __launch_bounds__(256) void kB_agg_tr(const float* __restrict__ b2,
                                                 const float* __restrict__ W3, int N) {
    __shared__ __align__(16) uint32_t sA[TILE * AROW];
    __shared__ __align__(16) uint32_t sB[64 * AROW];
    __shared__ float sb2[64];
    __shared__ float sdinv[TILE];
    int tid = threadIdx.x;
    int nodeBase = blockIdx.x * TILE;

    if (tid < 64) sb2[tid] = b2[tid];
    load_W_tf32(W3, sB);
    __syncthreads();   // sb2 visible to gather phase

    // aggregation: octet per node row; warp w covers rows w*16..w*16+15
    {
        int w    = tid >> 5;
        int lane = tid & 31;
        int oct  = lane >> 3;
        int l8   = lane & 7;
        #pragma unroll
        for (int j = 0; j < 4; j++) {
            int nl = w * 16 + j * 4 + oct;
            int d  = nodeBase + nl;
            float a[8] = {0.f, 0.f, 0.f, 0.f, 0.f, 0.f, 0.f, 0.f};
            float di = 0.0f;
            if (d < N) {
                acc_uint4(a, ((const uint4*)(g_m0 + (size_t)d * HDIM))[l8]);
                int i = g_rowptr[d], end = g_rowptr[d + 1];
                for (; i + 2 <= end; i += 2) {
                    int s0 = g_esrc[i], s1 = g_esrc[i + 1];
                    uint4 u0 = ((const uint4*)(g_m0 + (size_t)s0 * HDIM))[l8];
                    uint4 u1 = ((const uint4*)(g_m0 + (size_t)s1 * HDIM))[l8];
                    acc_uint4(a, u0);
                    acc_uint4(a, u1);
                }
                if (i < end) {
                    int s = g_esrc[i];
                    acc_uint4(a, ((const uint4*)(g_m0 + (size_t)s * HDIM))[l8]);
                }
                di = g_dinv[d];
            }
            if (l8 == 0) sdinv[nl] = di;
            const float* bb = &sb2[l8 * 8];
            uint32_t* o = sA + nl * AROW + l8 * 8;
            #pragma unroll
            for (int k = 0; k < 8; k++)
                o[k] = f2tf32(fmaxf(bb[k] + di * a[k], 0.f));
        }
    }
    __syncthreads();

    gemm_mma128(sA, sB, sdinv, g_m1, nodeBase, N);
}

// ---------------- kC: fused layer-3 aggregation + relu + pool partials ----------------
__global__ __launch_bounds__(256) void kC_agg_pool(const float* __restrict__ b, int N) {
    int tid  = threadIdx.x;
    int w    = tid >> 5;
    int lane = tid & 31;
    int oct  = lane >> 3;
    int l8   = lane & 7;

    float bb[8];
    #pragma unroll
    for (int k = 0; k < 8; k++) bb[k] = b[l8 * 8 + k];
    float acc[8] = {0.f, 0.f, 0.f, 0.f, 0.f, 0.f, 0.f, 0.f};

    int stride = gridDim.x * 32;
    for (int d = blockIdx.x * 32 + w * 4 + oct; d < N; d += stride) {
        float a[8] = {0.f, 0.f, 0.f, 0.f, 0.f, 0.f, 0.f, 0.f};
        acc_uint4(a, ((const uint4*)(g_m1 + (size_t)d * HDIM))[l8]);
        int i = g_rowptr[d], end = g_rowptr[d + 1];
        for (; i + 2 <= end; i += 2) {
            int s0 = g_esrc[i], s1 = g_esrc[i + 1];
            uint4 u0 = ((const uint4*)(g_m1 + (size_t)s0 * HDIM))[l8];
            uint4 u1 = ((const uint4*)(g_m1 + (size_t)s1 * HDIM))[l8];
            acc_uint4(a, u0);
            acc_uint4(a, u1);
        }
        if (i < end) {
            int s = g_esrc[i];
            acc_uint4(a, ((const uint4*)(g_m1 + (size_t)s * HDIM))[l8]);
        }
        float di = g_dinv[d];
        #pragma unroll
        for (int k = 0; k < 8; k++)
            acc[k] += fmaxf(bb[k] + di * a[k], 0.f);
    }

    __shared__ float sp[64];
    if (tid < 64) sp[tid] = 0.0f;
    __syncthreads();
    #pragma unroll
    for (int k = 0; k < 8; k++)
        atomicAdd(&sp[l8 * 8 + k], acc[k]);
    __syncthreads();
    if (tid < 64) g_partial[(size_t)blockIdx.x * HDIM + tid] = sp[tid];
}

__global__ __launch_bounds__(256) void k_reduce(int numPartial) {
    __shared__ float sdata[256];
    int c = blockIdx.x;
    float s = 0.0f;
    for (int i = threadIdx.x; i < numPartial; i += 256)
        s += g_partial[(size_t)i * HDIM + c];
    sdata[threadIdx.x] = s;
    __syncthreads();
    for (int off = 128; off > 0; off >>= 1) {
        if (threadIdx.x < off) sdata[threadIdx.x] += sdata[threadIdx.x + off];
        __syncthreads();
    }
    if (threadIdx.x == 0) g_pool[c] = sdata[0];
}

__global__ void k_final(const float* __restrict__ Wfc, const float* __restrict__ bfc,
                        float* __restrict__ out, int N) {
    int c = threadIdx.x;
    if (c >= 24) return;
    float invN = 1.0f / (float)N;
    float acc = bfc[c];
    #pragma unroll
    for (int k = 0; k < 64; k++)
        acc += (g_pool[k] * invN) * Wfc[k * 24 + c];
    out[c] = tanhf(acc);
}

// ---------------- launch ----------------
extern "C" void kernel_launch(void* const* d_in, const int* in_sizes, int n_in,
                              void* d_out, int out_size) {
    const float* x   = (const float*)d_in[0];
    const int*   ei  = (const int*)d_in[1];   // int32 (JAX x64 disabled)
    const float* W1  = (const float*)d_in[3];
    const float* b1  = (const float*)d_in[4];
    const float* W2  = (const float*)d_in[5];
    const float* b2  = (const float*)d_in[6];
    const float* W3  = (const float*)d_in[7];
    const float* b3  = (const float*)d_in[8];
    const float* Wfc = (const float*)d_in[9];
    const float* bfc = (const float*)d_in[10];
    float* out = (float*)d_out;

    int N = in_sizes[0] / 3;
    int E = in_sizes[1] / 2;

    const int T = 256;
    int nbN    = (N + T - 1) / T;
    int nbE    = (E + T - 1) / T;
    int nbTr   = (N + TILE - 1) / TILE;
    int nbScan = (N + SCAN_ITEMS - 1) / SCAN_ITEMS;

    // CSR + normalization
    k_zero<<<nbN, T>>>(N);
    k_hist<<<nbE, T>>>(ei, E);
    k_scan_local<<<nbScan, SCAN_T>>>(N);
    k_scan_bsums<<<1, SCAN_T>>>(nbScan);
    k_scan_add_prep<<<nbN, T>>>(x, N, E);
    k_fill<<<nbE, T>>>(ei, E);

    // fused x-agg + layer1 + layer2 transforms -> m0 (tf32 tensor cores, 128-node tiles)
    kA_l12<<<nbTr, T>>>(W1, b1, W2, N);

    // fused layer2 aggregation + layer3 transform -> m1 (128-node tiles)
    kB_agg_tr<<<nbTr, T>>>(b2, W3, N);

    // fused layer3 aggregation + relu + mean-pool
    kC_agg_pool<<<POOL_BLOCKS, T>>>(b3, N);

    // reduce + FC + tanh
    k_reduce<<<64, 256>>>(POOL_BLOCKS);
    k_final<<<1, 32>>>(Wfc, bfc, out, N);
}